// round 2
// baseline (speedup 1.0000x reference)
#include <cuda_runtime.h>
#include <cmath>

// ---------------- problem constants ----------------
#define B_    64
#define S_    32
#define INF_  512
#define N1_   1229            // inter
#define N2_   819             // command
#define N3_   512             // motor
#define NU_   2560            // N1+N2+N3
#define K1_   1741            // 512+1229
#define K2_   2048            // 1229+819
#define K3_   1331            // 819+512
#define NHP1_ 1248            // N1 padded to 32
#define NHP2_ 832
#define NHP3_ 512
#define NC1_  (4*NHP1_)       // 4992 (4 heads concatenated)
#define NC2_  (4*NHP2_)       // 3328
#define NC3_  (4*NHP3_)       // 2048
#define KS1_  3               // k-splits per cell so tiles ~= 148
#define KS2_  5
#define KS3_  9
#define NT1_  39              // n-tiles (32 cols each)
#define NT2_  26
#define NT3_  16
#define NBLK_ 148
#define NTHR_ 256

// ---------------- device scratch (static, no allocation) ----------------
__device__ float g_Wt1[K1_ * NC1_];           // masked, transposed, head-concat (k-major)
__device__ float g_Wt2[K2_ * NC2_];
__device__ float g_Wt3[K3_ * NC3_];
__device__ float g_xpre[S_ * B_ * NC1_];      // precomputed x-part of cell1 (+bias)
__device__ float g_P1[KS1_ * 4 * B_ * NHP1_]; // k-split partial sums
__device__ float g_P2[KS2_ * 4 * B_ * NHP2_];
__device__ float g_P3[KS3_ * 4 * B_ * NHP3_];
__device__ float g_H1[2][B_ * N1_];
__device__ float g_H2[2][B_ * N2_];
__device__ float g_H3[2][B_ * N3_];
__device__ float g_O1[B_ * N1_];
__device__ float g_O2[B_ * N2_];
__device__ unsigned g_bar_cnt;                // grid barrier state (relative-epoch: replay-safe)
__device__ volatile unsigned g_bar_epoch;

// ---------------- grid-wide barrier (deterministic, spin on L2) ----------------
__device__ __forceinline__ void grid_barrier() {
    __threadfence();
    __syncthreads();
    if (threadIdx.x == 0) {
        unsigned e = g_bar_epoch;
        if (atomicAdd(&g_bar_cnt, 1u) == gridDim.x - 1u) {
            g_bar_cnt = 0u;
            __threadfence();
            g_bar_epoch = e + 1u;
        } else {
            while (g_bar_epoch == e) { }
        }
    }
    __syncthreads();
}

// ---------------- weight premask + transpose (W[n,k]*M[n,k] -> Wt[k, head*Nhp+n]) ----------------
__global__ void k_prep(const float* __restrict__ Wg, const float* __restrict__ Wh,
                       const float* __restrict__ Wfg, const float* __restrict__ Wfh,
                       const float* __restrict__ Msk,
                       int cell, int Nh, int K, int Nhp, int Nc, int ktiles, int ntiles) {
    float* Wt = (cell == 0) ? g_Wt1 : (cell == 1) ? g_Wt2 : g_Wt3;
    __shared__ float s[32][33];
    int tile = blockIdx.x;
    int hd = tile / (ktiles * ntiles); tile -= hd * (ktiles * ntiles);
    int kt = tile / ntiles, nt = tile - kt * ntiles;
    const float* W = (hd == 0) ? Wg : (hd == 1) ? Wh : (hd == 2) ? Wfg : Wfh;
    int k0 = kt * 32, n0 = nt * 32;
    int tx = threadIdx.x, ty = threadIdx.y;
    int n = n0 + ty, k = k0 + tx;
    float v = 0.f;
    if (n < Nh && k < K) v = W[(size_t)n * K + k] * Msk[(size_t)n * K + k];
    s[ty][tx] = v;
    __syncthreads();
    int kk = k0 + ty, nn = n0 + tx;                 // nn < Nhp by construction
    if (kk < K) Wt[(size_t)kk * Nc + hd * Nhp + nn] = s[tx][ty];
}

// ---------------- hidden-state init from h0 ----------------
__global__ void k_init(const float* __restrict__ h0) {
    int i = blockIdx.x * blockDim.x + threadIdx.x;
    if (i < B_ * NU_) {
        int m = i / NU_, c = i - m * NU_;
        float v = h0[i];
        if (c < N1_)            g_H1[0][m * N1_ + c] = v;
        else if (c < N1_ + N2_) g_H2[0][m * N2_ + (c - N1_)] = v;
        else                    g_H3[0][m * N3_ + (c - N1_ - N2_)] = v;
    }
}

// ---------------- parallel precompute of cell1 x-part for all timesteps (+bias) ----------------
__global__ __launch_bounds__(NTHR_) void k_xpre(const float* __restrict__ x,
                                                const float* __restrict__ bg, const float* __restrict__ bh,
                                                const float* __restrict__ bfg, const float* __restrict__ bfh) {
    __shared__ float zs[64 * 128];
    const int CT_ = NC1_ / 32;                       // 156 column tiles
    int t = blockIdx.x / CT_;
    int ct = blockIdx.x - t * CT_;
    int mg = threadIdx.x >> 5, cl = threadIdx.x & 31;
    int col = ct * 32 + cl;
    float acc[8];
#pragma unroll
    for (int i = 0; i < 8; i++) acc[i] = 0.f;
    for (int k0 = 0; k0 < INF_; k0 += 128) {
        __syncthreads();
        for (int idx = threadIdx.x; idx < 64 * 128; idx += NTHR_) {
            int m = idx >> 7, kl = idx & 127;
            zs[m * 128 + kl] = x[((size_t)m * S_ + t) * INF_ + k0 + kl];
        }
        __syncthreads();
        const float* wp = g_Wt1 + (size_t)k0 * NC1_ + col;
#pragma unroll 4
        for (int kl = 0; kl < 128; kl++) {
            float w = __ldg(wp); wp += NC1_;
            const float* zr = &zs[(mg * 8) * 128 + kl];
#pragma unroll
            for (int i = 0; i < 8; i++) acc[i] += w * zr[i * 128];
        }
    }
    int hd = col / NHP1_, n = col - hd * NHP1_;
    float b = 0.f;
    if (n < N1_) {
        const float* bp = (hd == 0) ? bg : (hd == 1) ? bh : (hd == 2) ? bfg : bfh;
        b = bp[n];
    }
#pragma unroll
    for (int i = 0; i < 8; i++) {
        int m = mg * 8 + i;
        g_xpre[((size_t)t * 64 + m) * NC1_ + col] = acc[i] + b;
    }
}

// ---------------- GEMM phase: out partials P[ks][h][m][Nhp] over its k-chunk ----------------
__device__ void gemm_phase(float* zs,
                           const float* __restrict__ z0, int z0c,
                           const float* __restrict__ z1, int z1c,
                           const float* __restrict__ Wb, int ldw, int Nhp,
                           float* __restrict__ P, int K, int ksplit, int ntiles) {
    int mg = threadIdx.x >> 5, nl = threadIdx.x & 31;
    int tiles = ksplit * ntiles;
    for (int tile = blockIdx.x; tile < tiles; tile += gridDim.x) {
        int ks = tile / ntiles, nt = tile - ks * ntiles;
        int kb = (int)((long)K * ks / ksplit);
        int ke = (int)((long)K * (ks + 1) / ksplit);
        float a0[8], a1[8], a2[8], a3[8];
#pragma unroll
        for (int i = 0; i < 8; i++) { a0[i] = 0.f; a1[i] = 0.f; a2[i] = 0.f; a3[i] = 0.f; }
        for (int k0 = kb; k0 < ke; k0 += 128) {
            int kt = min(128, ke - k0);
            __syncthreads();
            for (int idx = threadIdx.x; idx < 64 * 128; idx += NTHR_) {
                int m = idx >> 7, kl = idx & 127;
                int kg = k0 + kl;
                float v = 0.f;
                if (kl < kt) {
                    v = (kg < z0c) ? __ldcg(&z0[(size_t)m * z0c + kg])
                                   : __ldcg(&z1[(size_t)m * z1c + (kg - z0c)]);
                }
                zs[m * 128 + kl] = v;
            }
            __syncthreads();
            const float* wp = Wb + (size_t)k0 * ldw + nt * 32 + nl;
#pragma unroll 2
            for (int kl = 0; kl < kt; kl++) {
                float w0 = __ldg(wp), w1 = __ldg(wp + Nhp), w2 = __ldg(wp + 2 * Nhp), w3 = __ldg(wp + 3 * Nhp);
                wp += ldw;
                const float* zr = &zs[(mg * 8) * 128 + kl];
#pragma unroll
                for (int i = 0; i < 8; i++) {
                    float zv = zr[i * 128];
                    a0[i] += w0 * zv; a1[i] += w1 * zv; a2[i] += w2 * zv; a3[i] += w3 * zv;
                }
            }
        }
        int n = nt * 32 + nl;
        size_t base = (size_t)(ks * 4) * 64 * Nhp + n;
#pragma unroll
        for (int i = 0; i < 8; i++) {
            int m = mg * 8 + i;
            P[base + (size_t)(0 * 64 + m) * Nhp] = a0[i];
            P[base + (size_t)(1 * 64 + m) * Nhp] = a1[i];
            P[base + (size_t)(2 * 64 + m) * Nhp] = a2[i];
            P[base + (size_t)(3 * 64 + m) * Nhp] = a3[i];
        }
    }
}

// ---------------- fused reduce + bias + CfC pointwise ----------------
__device__ void pointwise_phase(const float* __restrict__ P, int ksplit, int Nhp, int Nh,
                                const float* __restrict__ xpre,     // cell1 only (bias folded), else null
                                const float* __restrict__ bg, const float* __restrict__ bh,
                                const float* __restrict__ bfg, const float* __restrict__ bfh,
                                float ts,
                                float* __restrict__ o, float* __restrict__ hq,
                                float* __restrict__ y, int t) {
    int tot = B_ * Nh;
    for (int idx = blockIdx.x * blockDim.x + threadIdx.x; idx < tot; idx += gridDim.x * blockDim.x) {
        int m = idx / Nh, n = idx - m * Nh;
        float s0 = 0.f, s1 = 0.f, s2 = 0.f, s3 = 0.f;
        for (int ks = 0; ks < ksplit; ks++) {
            size_t base = ((size_t)(ks * 4) * 64 + m) * Nhp + n;
            s0 += __ldcg(&P[base]);
            s1 += __ldcg(&P[base + (size_t)64 * Nhp]);
            s2 += __ldcg(&P[base + (size_t)128 * Nhp]);
            s3 += __ldcg(&P[base + (size_t)192 * Nhp]);
        }
        if (xpre) {
            const float* xr = &xpre[(size_t)m * NC1_ + n];
            s0 += __ldg(xr); s1 += __ldg(xr + NHP1_); s2 += __ldg(xr + 2 * NHP1_); s3 += __ldg(xr + 3 * NHP1_);
        } else {
            s0 += __ldg(&bg[n]); s1 += __ldg(&bh[n]); s2 += __ldg(&bfg[n]); s3 += __ldg(&bfh[n]);
        }
        float gv = tanhf(s0), hv = tanhf(s1);
        float gate = 1.f / (1.f + expf(-(s2 + ts * s3)));
        float ov = gv * (1.f - gate) + hv * gate;
        if (o) o[idx] = ov;
        hq[idx] = ov;
        if (y) y[((size_t)m * S_ + t) * N3_ + n] = ov;
    }
}

// ---------------- persistent time-loop kernel ----------------
__global__ __launch_bounds__(NTHR_) void k_main(const float* __restrict__ tspans,
                                                float* __restrict__ out,
                                                const float* __restrict__ bg2, const float* __restrict__ bh2,
                                                const float* __restrict__ bfg2, const float* __restrict__ bfh2,
                                                const float* __restrict__ bg3, const float* __restrict__ bh3,
                                                const float* __restrict__ bfg3, const float* __restrict__ bfh3) {
    __shared__ float zs[64 * 128];
    for (int t = 0; t < S_; t++) {
        int p = t & 1, q = p ^ 1;
        float ts = __ldg(&tspans[t]);

        // cell 1 (recurrent part only; x-part precomputed in g_xpre)
        gemm_phase(zs, g_H1[p], N1_, (const float*)nullptr, 0,
                   g_Wt1 + (size_t)INF_ * NC1_, NC1_, NHP1_, g_P1, N1_, KS1_, NT1_);
        grid_barrier();
        pointwise_phase(g_P1, KS1_, NHP1_, N1_,
                        g_xpre + (size_t)t * 64 * NC1_, nullptr, nullptr, nullptr, nullptr,
                        ts, g_O1, g_H1[q], nullptr, t);
        grid_barrier();

        // cell 2: z = [o1 | h2]
        gemm_phase(zs, g_O1, N1_, g_H2[p], N2_,
                   g_Wt2, NC2_, NHP2_, g_P2, K2_, KS2_, NT2_);
        grid_barrier();
        pointwise_phase(g_P2, KS2_, NHP2_, N2_,
                        nullptr, bg2, bh2, bfg2, bfh2,
                        ts, g_O2, g_H2[q], nullptr, t);
        grid_barrier();

        // cell 3: z = [o2 | h3]
        gemm_phase(zs, g_O2, N2_, g_H3[p], N3_,
                   g_Wt3, NC3_, NHP3_, g_P3, K3_, KS3_, NT3_);
        grid_barrier();
        pointwise_phase(g_P3, KS3_, NHP3_, N3_,
                        nullptr, bg3, bh3, bfg3, bfh3,
                        ts, nullptr, g_H3[q], out, t);
        grid_barrier();
    }
    // h_final = concat(h1,h2,h3) at parity 0 (S even)
    float* hf = out + (size_t)B_ * S_ * N3_;
    for (int i = blockIdx.x * blockDim.x + threadIdx.x; i < B_ * NU_; i += gridDim.x * blockDim.x) {
        int m = i / NU_, c = i - m * NU_;
        float v;
        if (c < N1_)            v = __ldcg(&g_H1[0][m * N1_ + c]);
        else if (c < N1_ + N2_) v = __ldcg(&g_H2[0][m * N2_ + (c - N1_)]);
        else                    v = __ldcg(&g_H3[0][m * N3_ + (c - N1_ - N2_)]);
        hf[i] = v;
    }
}

// ---------------- launch ----------------
extern "C" void kernel_launch(void* const* d_in, const int* in_sizes, int n_in,
                              void* d_out, int out_size) {
    const float* x    = (const float*)d_in[0];
    const float* h0   = (const float*)d_in[1];
    const float* tsp  = (const float*)d_in[2];
    const float* Wg1  = (const float*)d_in[3];
    const float* Wh1  = (const float*)d_in[4];
    const float* Wfg1 = (const float*)d_in[5];
    const float* Wfh1 = (const float*)d_in[6];
    const float* bg1  = (const float*)d_in[7];
    const float* bh1  = (const float*)d_in[8];
    const float* bfg1 = (const float*)d_in[9];
    const float* bfh1 = (const float*)d_in[10];
    const float* msk1 = (const float*)d_in[11];
    const float* Wg2  = (const float*)d_in[12];
    const float* Wh2  = (const float*)d_in[13];
    const float* Wfg2 = (const float*)d_in[14];
    const float* Wfh2 = (const float*)d_in[15];
    const float* bg2  = (const float*)d_in[16];
    const float* bh2  = (const float*)d_in[17];
    const float* bfg2 = (const float*)d_in[18];
    const float* bfh2 = (const float*)d_in[19];
    const float* msk2 = (const float*)d_in[20];
    const float* Wg3  = (const float*)d_in[21];
    const float* Wh3  = (const float*)d_in[22];
    const float* Wfg3 = (const float*)d_in[23];
    const float* Wfh3 = (const float*)d_in[24];
    const float* bg3  = (const float*)d_in[25];
    const float* bh3  = (const float*)d_in[26];
    const float* bfg3 = (const float*)d_in[27];
    const float* bfh3 = (const float*)d_in[28];
    const float* msk3 = (const float*)d_in[29];
    float* out = (float*)d_out;

    dim3 tb(32, 32);
    // premask + transpose (k-major, 4 heads concat, zero-padded cols)
    {
        int kt = (K1_ + 31) / 32, nt = NHP1_ / 32;
        k_prep<<<4 * kt * nt, tb>>>(Wg1, Wh1, Wfg1, Wfh1, msk1, 0, N1_, K1_, NHP1_, NC1_, kt, nt);
    }
    {
        int kt = (K2_ + 31) / 32, nt = NHP2_ / 32;
        k_prep<<<4 * kt * nt, tb>>>(Wg2, Wh2, Wfg2, Wfh2, msk2, 1, N2_, K2_, NHP2_, NC2_, kt, nt);
    }
    {
        int kt = (K3_ + 31) / 32, nt = NHP3_ / 32;
        k_prep<<<4 * kt * nt, tb>>>(Wg3, Wh3, Wfg3, Wfh3, msk3, 2, N3_, K3_, NHP3_, NC3_, kt, nt);
    }
    // hidden state init
    k_init<<<(B_ * NU_ + 255) / 256, 256>>>(h0);
    // parallel x-part precompute for cell1, all timesteps
    k_xpre<<<S_ * (NC1_ / 32), NTHR_>>>(x, bg1, bh1, bfg1, bfh1);
    // persistent sequential loop
    k_main<<<NBLK_, NTHR_>>>(tsp, out,
                             bg2, bh2, bfg2, bfh2,
                             bg3, bh3, bfg3, bfh3);
    (void)in_sizes; (void)n_in; (void)out_size;
}

// round 7
// speedup vs baseline: 7.4478x; 7.4478x over previous
#include <cuda_runtime.h>
#include <cuda_bf16.h>
#include <mma.h>
#include <cmath>
#include <cstdint>

using namespace nvcuda;

// ---------------- problem constants ----------------
#define B_    64
#define S_    32
#define INF_  512
#define N1_   1229
#define N2_   819
#define N3_   512
#define NU_   2560
#define K1_   1741
#define K2_   2048
#define K3_   1331
#define NHP1_ 1248
#define NHP2_ 832
#define NHP3_ 512
#define NC1_  4992
#define NC2_  3328
#define NC3_  2048
#define T1_   39
#define T2_   26
#define T3_   16
#define C1_   28              // ceil(K/64) chunks; Z1 pitch 1792
#define C2_   32              // Z2 pitch 2048
#define C3_   21              // Z3 pitch 1344
#define Z1P_  1792
#define Z2P_  2048
#define Z3P_  1344
#define KS1_  3               // tiles: 117 / 130 / 144 on 148 CTAs
#define KS2_  5
#define KS3_  9
#define NBLK_ 148
#define NTHR_ 256

// smem buffer layout (per buffer): Ahi[128x72] Alo Bhi[64x72] Blo
#define A_PL_   18432         // 128*144 bytes
#define B_PL_   9216          // 64*144 bytes
#define BUFSZ_  55296         // 2*A_PL_ + 2*B_PL_
#define SMEM_RAW_ (2 * BUFSZ_ + 256)

// ---------------- device scratch ----------------
__device__ __nv_bfloat16 g_W1hi[(size_t)T1_ * C1_ * 8192];
__device__ __nv_bfloat16 g_W1lo[(size_t)T1_ * C1_ * 8192];
__device__ __nv_bfloat16 g_W2hi[(size_t)T2_ * C2_ * 8192];
__device__ __nv_bfloat16 g_W2lo[(size_t)T2_ * C2_ * 8192];
__device__ __nv_bfloat16 g_W3hi[(size_t)T3_ * C3_ * 8192];
__device__ __nv_bfloat16 g_W3lo[(size_t)T3_ * C3_ * 8192];
__device__ __nv_bfloat16 g_Xhi[(size_t)S_ * B_ * INF_];
__device__ __nv_bfloat16 g_Xlo[(size_t)S_ * B_ * INF_];
__device__ __nv_bfloat16 g_Z1h[B_ * Z1P_], g_Z1l[B_ * Z1P_];
__device__ __nv_bfloat16 g_Z2h[B_ * Z2P_], g_Z2l[B_ * Z2P_];
__device__ __nv_bfloat16 g_Z3h[B_ * Z3P_], g_Z3l[B_ * Z3P_];
__device__ float g_P1[(size_t)KS1_ * B_ * NC1_];
__device__ float g_P2[(size_t)KS2_ * B_ * NC2_];
__device__ float g_P3[(size_t)KS3_ * B_ * NC3_];
__device__ float g_H1f[B_ * N1_], g_H2f[B_ * N2_], g_H3f[B_ * N3_];
__device__ unsigned g_bar_cnt;
__device__ volatile unsigned g_bar_epoch;

// ---------------- async copy helpers ----------------
#define CP16(dst, src)  asm volatile("cp.async.ca.shared.global [%0], [%1], 16;" :: "r"(dst), "l"(src))
#define CPCOMMIT()      asm volatile("cp.async.commit_group;")
#define CPWAIT0()       asm volatile("cp.async.wait_group 0;")
#define CPWAIT1()       asm volatile("cp.async.wait_group 1;")

// ---------------- grid-wide barrier ----------------
__device__ __forceinline__ void grid_barrier() {
    __threadfence();
    __syncthreads();
    if (threadIdx.x == 0) {
        unsigned e = g_bar_epoch;
        if (atomicAdd(&g_bar_cnt, 1u) == gridDim.x - 1u) {
            g_bar_cnt = 0u;
            __threadfence();
            g_bar_epoch = e + 1u;
        } else {
            while (g_bar_epoch == e) { }
        }
    }
    __syncthreads();
}

// ---------------- weight prep: mask, split bf16 hi/lo, flat [tile][chunk][128][64] ----------------
__global__ void k_prep(const float* __restrict__ Wg, const float* __restrict__ Wh,
                       const float* __restrict__ Wfg, const float* __restrict__ Wfh,
                       const float* __restrict__ Msk,
                       __nv_bfloat16* __restrict__ Dhi, __nv_bfloat16* __restrict__ Dlo,
                       int Nh, int K, int Nhp, int nchunks) {
    int blk = blockIdx.x;
    int tile = blk / nchunks, chunk = blk - tile * nchunks;
    size_t base = (size_t)blk * 8192;
    for (int e = threadIdx.x; e < 8192; e += blockDim.x) {
        int row = e >> 6, col = e & 63;
        int nc = tile * 128 + row;
        int hd = nc / Nhp, n = nc - hd * Nhp;
        int kk = chunk * 64 + col;
        float v = 0.f;
        if (n < Nh && kk < K) {
            const float* W = (hd == 0) ? Wg : (hd == 1) ? Wh : (hd == 2) ? Wfg : Wfh;
            v = W[(size_t)n * K + kk] * Msk[(size_t)n * K + kk];
        }
        __nv_bfloat16 hi = __float2bfloat16(v);
        __nv_bfloat16 lo = __float2bfloat16(v - __bfloat162float(hi));
        Dhi[base + e] = hi;
        Dlo[base + e] = lo;
    }
}

// ---------------- x split to bf16 hi/lo planes, [t][batch][512] ----------------
__global__ void k_xprep(const float* __restrict__ x) {
    int i = blockIdx.x * blockDim.x + threadIdx.x;
    if (i < S_ * B_ * INF_) {
        int f = i & (INF_ - 1);
        int r = i >> 9;           // t*64 + ? no: decode below
        int t = r / B_, b = r - t * B_;
        float v = x[((size_t)b * S_ + t) * INF_ + f];
        __nv_bfloat16 hi = __float2bfloat16(v);
        g_Xhi[i] = hi;
        g_Xlo[i] = __float2bfloat16(v - __bfloat162float(hi));
    }
}

// ---------------- init: scatter h0 into fp32 + bf16 planes, zero pad cols ----------------
__global__ void k_init(const float* __restrict__ h0) {
    int stride = gridDim.x * blockDim.x;
    for (int i = blockIdx.x * blockDim.x + threadIdx.x; i < B_ * NU_; i += stride) {
        int m = i / NU_, c = i - m * NU_;
        float v = h0[i];
        __nv_bfloat16 hi = __float2bfloat16(v);
        __nv_bfloat16 lo = __float2bfloat16(v - __bfloat162float(hi));
        if (c < N1_) {
            g_H1f[m * N1_ + c] = v;
            g_Z1h[m * Z1P_ + INF_ + c] = hi;  g_Z1l[m * Z1P_ + INF_ + c] = lo;
        } else if (c < N1_ + N2_) {
            int cc = c - N1_;
            g_H2f[m * N2_ + cc] = v;
            g_Z2h[m * Z2P_ + N1_ + cc] = hi;  g_Z2l[m * Z2P_ + N1_ + cc] = lo;
        } else {
            int cc = c - N1_ - N2_;
            g_H3f[m * N3_ + cc] = v;
            g_Z3h[m * Z3P_ + N2_ + cc] = hi;  g_Z3l[m * Z3P_ + N2_ + cc] = lo;
        }
    }
    // zero pad columns (avoid NaN * 0)
    for (int i = blockIdx.x * blockDim.x + threadIdx.x; i < B_ * (Z1P_ - K1_); i += stride) {
        int m = i / (Z1P_ - K1_), c = K1_ + (i - m * (Z1P_ - K1_));
        g_Z1h[m * Z1P_ + c] = __float2bfloat16(0.f);
        g_Z1l[m * Z1P_ + c] = __float2bfloat16(0.f);
    }
    for (int i = blockIdx.x * blockDim.x + threadIdx.x; i < B_ * (Z3P_ - K3_); i += stride) {
        int m = i / (Z3P_ - K3_), c = K3_ + (i - m * (Z3P_ - K3_));
        g_Z3h[m * Z3P_ + c] = __float2bfloat16(0.f);
        g_Z3l[m * Z3P_ + c] = __float2bfloat16(0.f);
    }
}

// ---------------- chunk staging into smem via cp.async ----------------
__device__ __forceinline__ void stage_chunk(uint32_t sb,
        const __nv_bfloat16* __restrict__ Whi, const __nv_bfloat16* __restrict__ Wlo,
        size_t wbase,
        const __nv_bfloat16* __restrict__ zh, const __nv_bfloat16* __restrict__ zl,
        int zstride, int colbase) {
    int tid = threadIdx.x;
#pragma unroll
    for (int i = 0; i < 8; i++) {                 // A: 32KB
        int e = tid + i * 256;
        int plane = e >> 10, r = (e >> 3) & 127, u = e & 7;
        const char* g = (const char*)((plane ? Wlo : Whi) + wbase) + r * 128 + u * 16;
        CP16(sb + plane * A_PL_ + r * 144 + u * 16, g);
    }
#pragma unroll
    for (int i = 0; i < 4; i++) {                 // B: 16KB
        int e = tid + i * 256;
        int plane = e >> 9, r = (e >> 3) & 63, u = e & 7;
        const char* g = (const char*)((plane ? zl : zh) + (size_t)r * zstride + colbase) + u * 16;
        CP16(sb + 2 * A_PL_ + plane * B_PL_ + r * 144 + u * 16, g);
    }
}

// ---------------- GEMM phase (wmma bf16, split-hi/lo, reg accum) ----------------
typedef wmma::fragment<wmma::matrix_a, 16, 16, 16, __nv_bfloat16, wmma::row_major> FragA;
typedef wmma::fragment<wmma::matrix_b, 16, 16, 16, __nv_bfloat16, wmma::col_major> FragB;
typedef wmma::fragment<wmma::accumulator, 16, 16, 16, float> FragC;

__device__ void gemm_cell(char* smc, uint32_t smb,
        const __nv_bfloat16* __restrict__ Whi, const __nv_bfloat16* __restrict__ Wlo,
        int nchunks, int ntiles, int ksplit,
        const __nv_bfloat16* __restrict__ xh, const __nv_bfloat16* __restrict__ xl,
        int xstride, int xchunks,
        const __nv_bfloat16* __restrict__ zh, const __nv_bfloat16* __restrict__ zl,
        int zstride,
        float* __restrict__ P, int NC) {
    int tl = blockIdx.x;
    if (tl >= ksplit * ntiles) return;
    int ks = tl / ntiles, nt = tl - ks * ntiles;
    int cb = nchunks * ks / ksplit, ce = nchunks * (ks + 1) / ksplit;
    int wid = threadIdx.x >> 5;
    int m0 = (wid & 3) * 32, n0 = (wid >> 2) * 32;

    FragC acc[2][2];
#pragma unroll
    for (int mi = 0; mi < 2; mi++)
#pragma unroll
        for (int ni = 0; ni < 2; ni++) wmma::fill_fragment(acc[mi][ni], 0.f);

    {
        bool ux = cb < xchunks;
        stage_chunk(smb, Whi, Wlo, (size_t)(nt * nchunks + cb) * 8192,
                    ux ? xh : zh, ux ? xl : zl, ux ? xstride : zstride, cb * 64);
        CPCOMMIT();
    }
    for (int c = cb; c < ce; c++) {
        uint32_t b = (uint32_t)(c - cb) & 1u;
        if (c + 1 < ce) {
            int cn = c + 1;
            bool ux = cn < xchunks;
            stage_chunk(smb + (b ^ 1u) * BUFSZ_, Whi, Wlo, (size_t)(nt * nchunks + cn) * 8192,
                        ux ? xh : zh, ux ? xl : zl, ux ? xstride : zstride, cn * 64);
            CPCOMMIT();
            CPWAIT1();
        } else {
            CPWAIT0();
        }
        __syncthreads();
        const __nv_bfloat16* A_h = (const __nv_bfloat16*)(smc + b * BUFSZ_);
        const __nv_bfloat16* A_l = (const __nv_bfloat16*)(smc + b * BUFSZ_ + A_PL_);
        const __nv_bfloat16* B_h = (const __nv_bfloat16*)(smc + b * BUFSZ_ + 2 * A_PL_);
        const __nv_bfloat16* B_l = (const __nv_bfloat16*)(smc + b * BUFSZ_ + 2 * A_PL_ + B_PL_);
#pragma unroll
        for (int k = 0; k < 4; k++) {
            FragA ah[2], al[2];
            FragB bh[2], bl[2];
            wmma::load_matrix_sync(ah[0], A_h + (m0 +  0) * 72 + k * 16, 72);
            wmma::load_matrix_sync(ah[1], A_h + (m0 + 16) * 72 + k * 16, 72);
            wmma::load_matrix_sync(al[0], A_l + (m0 +  0) * 72 + k * 16, 72);
            wmma::load_matrix_sync(al[1], A_l + (m0 + 16) * 72 + k * 16, 72);
            wmma::load_matrix_sync(bh[0], B_h + (n0 +  0) * 72 + k * 16, 72);
            wmma::load_matrix_sync(bh[1], B_h + (n0 + 16) * 72 + k * 16, 72);
            wmma::load_matrix_sync(bl[0], B_l + (n0 +  0) * 72 + k * 16, 72);
            wmma::load_matrix_sync(bl[1], B_l + (n0 + 16) * 72 + k * 16, 72);
#pragma unroll
            for (int mi = 0; mi < 2; mi++)
#pragma unroll
                for (int ni = 0; ni < 2; ni++) {
                    wmma::mma_sync(acc[mi][ni], ah[mi], bh[ni], acc[mi][ni]);
                    wmma::mma_sync(acc[mi][ni], ah[mi], bl[ni], acc[mi][ni]);
                    wmma::mma_sync(acc[mi][ni], al[mi], bh[ni], acc[mi][ni]);
                }
        }
        __syncthreads();
    }
    // store D^T partials: P[(ks*64 + batch)][NC] layout, col_major store
#pragma unroll
    for (int mi = 0; mi < 2; mi++)
#pragma unroll
        for (int ni = 0; ni < 2; ni++) {
            float* pp = P + (size_t)(ks * 64 + n0 + ni * 16) * NC + nt * 128 + m0 + mi * 16;
            wmma::store_matrix_sync(pp, acc[mi][ni], NC, wmma::mem_col_major);
        }
}

// ---------------- fused reduce + bias + CfC pointwise ----------------
__device__ void pointwise(const float* __restrict__ P, int ksplit, int NC, int Nhp, int Nh,
                          const float* __restrict__ bg, const float* __restrict__ bh,
                          const float* __restrict__ bfg, const float* __restrict__ bfh,
                          float ts, float* __restrict__ Hf,
                          __nv_bfloat16* __restrict__ d0h, __nv_bfloat16* __restrict__ d0l,
                          int d0s, int d0off,
                          __nv_bfloat16* __restrict__ d1h, __nv_bfloat16* __restrict__ d1l,
                          int d1s, int d1off,
                          float* __restrict__ y, int t) {
    int tot = B_ * Nh;
    for (int idx = blockIdx.x * blockDim.x + threadIdx.x; idx < tot; idx += gridDim.x * blockDim.x) {
        int m = idx / Nh, n = idx - m * Nh;
        float s0 = 0.f, s1 = 0.f, s2 = 0.f, s3 = 0.f;
        for (int ks = 0; ks < ksplit; ks++) {
            const float* pb = P + (size_t)(ks * 64 + m) * NC + n;
            s0 += __ldcg(pb);
            s1 += __ldcg(pb + Nhp);
            s2 += __ldcg(pb + 2 * Nhp);
            s3 += __ldcg(pb + 3 * Nhp);
        }
        s0 += __ldg(&bg[n]); s1 += __ldg(&bh[n]); s2 += __ldg(&bfg[n]); s3 += __ldg(&bfh[n]);
        float gv = tanhf(s0), hv = tanhf(s1);
        float gate = 1.f / (1.f + expf(-(s2 + ts * s3)));
        float ov = gv * (1.f - gate) + hv * gate;
        Hf[idx] = ov;
        __nv_bfloat16 hi = __float2bfloat16(ov);
        __nv_bfloat16 lo = __float2bfloat16(ov - __bfloat162float(hi));
        d0h[(size_t)m * d0s + d0off + n] = hi;
        d0l[(size_t)m * d0s + d0off + n] = lo;
        if (d1h) {
            d1h[(size_t)m * d1s + d1off + n] = hi;
            d1l[(size_t)m * d1s + d1off + n] = lo;
        }
        if (y) y[((size_t)m * S_ + t) * N3_ + n] = ov;
    }
}

// ---------------- persistent time-loop kernel ----------------
__global__ __launch_bounds__(NTHR_, 1)
void k_main(const float* __restrict__ tspans, float* __restrict__ out,
            const float* __restrict__ bg1, const float* __restrict__ bh1,
            const float* __restrict__ bfg1, const float* __restrict__ bfh1,
            const float* __restrict__ bg2, const float* __restrict__ bh2,
            const float* __restrict__ bfg2, const float* __restrict__ bfh2,
            const float* __restrict__ bg3, const float* __restrict__ bh3,
            const float* __restrict__ bfg3, const float* __restrict__ bfh3) {
    extern __shared__ char smraw[];
    uint32_t raw32;
    asm("{ .reg .u64 t; cvta.to.shared.u64 t, %1; cvt.u32.u64 %0, t; }" : "=r"(raw32) : "l"(smraw));
    uint32_t smb = (raw32 + 127u) & ~127u;
    char* smc = smraw + (smb - raw32);

    for (int t = 0; t < S_; t++) {
        float ts = __ldg(&tspans[t]);

        // cell 1: z = [x_t | h1]  (x chunks 0..7 from X planes, rest from Z1)
        gemm_cell(smc, smb, g_W1hi, g_W1lo, C1_, T1_, KS1_,
                  g_Xhi + (size_t)t * B_ * INF_, g_Xlo + (size_t)t * B_ * INF_, INF_, 8,
                  g_Z1h, g_Z1l, Z1P_, g_P1, NC1_);
        grid_barrier();
        pointwise(g_P1, KS1_, NC1_, NHP1_, N1_, bg1, bh1, bfg1, bfh1, ts, g_H1f,
                  g_Z1h, g_Z1l, Z1P_, INF_,     // o1 -> next-step h1
                  g_Z2h, g_Z2l, Z2P_, 0,        // o1 -> cell2 input
                  nullptr, t);
        grid_barrier();

        // cell 2: z = [o1 | h2] = Z2
        gemm_cell(smc, smb, g_W2hi, g_W2lo, C2_, T2_, KS2_,
                  nullptr, nullptr, 0, 0,
                  g_Z2h, g_Z2l, Z2P_, g_P2, NC2_);
        grid_barrier();
        pointwise(g_P2, KS2_, NC2_, NHP2_, N2_, bg2, bh2, bfg2, bfh2, ts, g_H2f,
                  g_Z2h, g_Z2l, Z2P_, N1_,      // o2 -> next-step h2
                  g_Z3h, g_Z3l, Z3P_, 0,        // o2 -> cell3 input
                  nullptr, t);
        grid_barrier();

        // cell 3: z = [o2 | h3] = Z3
        gemm_cell(smc, smb, g_W3hi, g_W3lo, C3_, T3_, KS3_,
                  nullptr, nullptr, 0, 0,
                  g_Z3h, g_Z3l, Z3P_, g_P3, NC3_);
        grid_barrier();
        pointwise(g_P3, KS3_, NC3_, NHP3_, N3_, bg3, bh3, bfg3, bfh3, ts, g_H3f,
                  g_Z3h, g_Z3l, Z3P_, N2_,      // o3 -> next-step h3
                  nullptr, nullptr, 0, 0,
                  out, t);
        grid_barrier();
    }

    // h_final = concat(h1,h2,h3) fp32
    float* hf = out + (size_t)B_ * S_ * N3_;
    for (int i = blockIdx.x * blockDim.x + threadIdx.x; i < B_ * NU_; i += gridDim.x * blockDim.x) {
        int m = i / NU_, c = i - m * NU_;
        float v;
        if (c < N1_)            v = __ldcg(&g_H1f[m * N1_ + c]);
        else if (c < N1_ + N2_) v = __ldcg(&g_H2f[m * N2_ + (c - N1_)]);
        else                    v = __ldcg(&g_H3f[m * N3_ + (c - N1_ - N2_)]);
        hf[i] = v;
    }
}

// ---------------- launch ----------------
extern "C" void kernel_launch(void* const* d_in, const int* in_sizes, int n_in,
                              void* d_out, int out_size) {
    const float* x    = (const float*)d_in[0];
    const float* h0   = (const float*)d_in[1];
    const float* tsp  = (const float*)d_in[2];
    const float* Wg1  = (const float*)d_in[3];
    const float* Wh1  = (const float*)d_in[4];
    const float* Wfg1 = (const float*)d_in[5];
    const float* Wfh1 = (const float*)d_in[6];
    const float* bg1  = (const float*)d_in[7];
    const float* bh1  = (const float*)d_in[8];
    const float* bfg1 = (const float*)d_in[9];
    const float* bfh1 = (const float*)d_in[10];
    const float* msk1 = (const float*)d_in[11];
    const float* Wg2  = (const float*)d_in[12];
    const float* Wh2  = (const float*)d_in[13];
    const float* Wfg2 = (const float*)d_in[14];
    const float* Wfh2 = (const float*)d_in[15];
    const float* bg2  = (const float*)d_in[16];
    const float* bh2  = (const float*)d_in[17];
    const float* bfg2 = (const float*)d_in[18];
    const float* bfh2 = (const float*)d_in[19];
    const float* msk2 = (const float*)d_in[20];
    const float* Wg3  = (const float*)d_in[21];
    const float* Wh3  = (const float*)d_in[22];
    const float* Wfg3 = (const float*)d_in[23];
    const float* Wfh3 = (const float*)d_in[24];
    const float* bg3  = (const float*)d_in[25];
    const float* bh3  = (const float*)d_in[26];
    const float* bfg3 = (const float*)d_in[27];
    const float* bfh3 = (const float*)d_in[28];
    const float* msk3 = (const float*)d_in[29];
    float* out = (float*)d_out;

    cudaFuncSetAttribute(k_main, cudaFuncAttributeMaxDynamicSharedMemorySize, SMEM_RAW_);

    __nv_bfloat16 *w1hi, *w1lo, *w2hi, *w2lo, *w3hi, *w3lo;
    cudaGetSymbolAddress((void**)&w1hi, g_W1hi);
    cudaGetSymbolAddress((void**)&w1lo, g_W1lo);
    cudaGetSymbolAddress((void**)&w2hi, g_W2hi);
    cudaGetSymbolAddress((void**)&w2lo, g_W2lo);
    cudaGetSymbolAddress((void**)&w3hi, g_W3hi);
    cudaGetSymbolAddress((void**)&w3lo, g_W3lo);

    k_prep<<<T1_ * C1_, NTHR_>>>(Wg1, Wh1, Wfg1, Wfh1, msk1, w1hi, w1lo, N1_, K1_, NHP1_, C1_);
    k_prep<<<T2_ * C2_, NTHR_>>>(Wg2, Wh2, Wfg2, Wfh2, msk2, w2hi, w2lo, N2_, K2_, NHP2_, C2_);
    k_prep<<<T3_ * C3_, NTHR_>>>(Wg3, Wh3, Wfg3, Wfh3, msk3, w3hi, w3lo, N3_, K3_, NHP3_, C3_);
    k_xprep<<<(S_ * B_ * INF_ + NTHR_ - 1) / NTHR_, NTHR_>>>(x);
    k_init<<<256, NTHR_>>>(h0);
    k_main<<<NBLK_, NTHR_, SMEM_RAW_>>>(tsp, out,
                                        bg1, bh1, bfg1, bfh1,
                                        bg2, bh2, bfg2, bfh2,
                                        bg3, bh3, bfg3, bfh3);
    (void)in_sizes; (void)n_in; (void)out_size;
}